// round 13
// baseline (speedup 1.0000x reference)
#include <cuda_runtime.h>
#include <cuda_fp16.h>

#define NN   100000
#define EE_MAX 1600000
#define ET_MAX (NN + EE_MAX)
#define FIN  165
#define HID  64

// ---------------- scratch (device globals; no allocation allowed) ------------
__device__ float4 g_h1f[NN * 8];        // layer-1 features fp16: 8 float4 = 32 half2 per row
__device__ float  g_s1[NN], g_d1[NN];
__device__ float4 g_p2[NN];             // packed (h2.x, h2.y, s2, d2)
__device__ int    g_deg[NN];
__device__ int    g_epos[EE_MAX];       // within-row position of each edge
__device__ int    g_rowptr[NN + 1];
__device__ int    g_esrc[ET_MAX];
__device__ int    g_bsum[128], g_boff[128];

// side stream + events for capture fork/join (host-side resources, module load)
struct HxStreams {
    cudaStream_t s2;
    cudaEvent_t evA, evB, evC;
    HxStreams() {
        cudaStreamCreateWithFlags(&s2, cudaStreamNonBlocking);
        cudaEventCreateWithFlags(&evA, cudaEventDisableTiming);
        cudaEventCreateWithFlags(&evB, cudaEventDisableTiming);
        cudaEventCreateWithFlags(&evC, cudaEventDisableTiming);
    }
};
static HxStreams g_hx;

// ------- GEMM1: h1 = x @ W1 (100000x165 @ 165x64), fused s1/d1 epilogue -----
__global__ void k_gemm1(const float* __restrict__ x, const float* __restrict__ W1,
                        const float* __restrict__ a1s, const float* __restrict__ a1d) {
    __shared__ float As[16][64];   // As[kk][row]
    __shared__ float Bs[16][64];   // Bs[kk][col]
    const int row0 = blockIdx.x * 64;
    const int tid  = threadIdx.x;        // 0..255
    const int tx   = tid & 15;           // col group (4 cols each)
    const int ty   = tid >> 4;           // row group (4 rows each)
    float acc[4][4] = {};

    for (int k0 = 0; k0 < FIN; k0 += 16) {
        #pragma unroll
        for (int i = 0; i < 4; i++) {
            int idx = tid * 4 + i;          // 0..1023
            int r  = idx >> 4;              // 0..63
            int kk = idx & 15;
            int gr = row0 + r, gk = k0 + kk;
            As[kk][r] = (gr < NN && gk < FIN) ? x[gr * FIN + gk] : 0.f;
        }
        #pragma unroll
        for (int i = 0; i < 4; i++) {
            int idx = tid * 4 + i;
            int kk = idx >> 6;              // 0..15
            int c  = idx & 63;
            int gk = k0 + kk;
            Bs[kk][c] = (gk < FIN) ? W1[gk * HID + c] : 0.f;
        }
        __syncthreads();
        #pragma unroll
        for (int kk = 0; kk < 16; kk++) {
            float a[4], b[4];
            #pragma unroll
            for (int i = 0; i < 4; i++) a[i] = As[kk][ty * 4 + i];
            #pragma unroll
            for (int i = 0; i < 4; i++) b[i] = Bs[kk][tx * 4 + i];
            #pragma unroll
            for (int i = 0; i < 4; i++)
                #pragma unroll
                for (int j = 0; j < 4; j++)
                    acc[i][j] += a[i] * b[j];
        }
        __syncthreads();
    }

    // store h1 as fp16 (cols tx*4 .. tx*4+3 -> half2 slots tx*2, tx*2+1 of the row)
    __half2* h1h = (__half2*)g_h1f;
    #pragma unroll
    for (int i = 0; i < 4; i++) {
        int gr = row0 + ty * 4 + i;
        if (gr < NN) {
            h1h[gr * 32 + tx * 2 + 0] = __floats2half2_rn(acc[i][0], acc[i][1]);
            h1h[gr * 32 + tx * 2 + 1] = __floats2half2_rn(acc[i][2], acc[i][3]);
        }
    }

    // fused epilogue: s1[r] = h[r]·a1s, d1[r] = h[r]·a1d (fp32, reduce 16 tx lanes)
    float4 as4 = *(const float4*)&a1s[tx * 4];
    float4 ad4 = *(const float4*)&a1d[tx * 4];
    #pragma unroll
    for (int i = 0; i < 4; i++) {
        float ps = acc[i][0] * as4.x + acc[i][1] * as4.y + acc[i][2] * as4.z + acc[i][3] * as4.w;
        float pd = acc[i][0] * ad4.x + acc[i][1] * ad4.y + acc[i][2] * ad4.z + acc[i][3] * ad4.w;
        #pragma unroll
        for (int o = 1; o < 16; o <<= 1) {
            ps += __shfl_xor_sync(~0u, ps, o);
            pd += __shfl_xor_sync(~0u, pd, o);
        }
        int gr = row0 + ty * 4 + i;
        if (tx == 0 && gr < NN) { g_s1[gr] = ps; g_d1[gr] = pd; }
    }
}

// ---------------- CSR construction ------------------------------------------
__global__ void k_zero_deg() {
    int i = blockIdx.x * blockDim.x + threadIdx.x;
    if (i < NN) g_deg[i] = 0;
}
__global__ void k_deg(const int* __restrict__ ei, int E) {
    int i = blockIdx.x * blockDim.x + threadIdx.x;
    if (i < E) {
        int d = ei[E + i];
        int p = 0;
        if (d >= 0 && d < NN) p = atomicAdd(&g_deg[d], 1);
        g_epos[i] = p;
    }
}
__global__ void k_scan1() {
    __shared__ int wsum[32];
    int i = blockIdx.x * 1024 + threadIdx.x;
    int t = threadIdx.x;
    int lane = t & 31, wid = t >> 5;
    int v = (i < NN) ? (g_deg[i] + 1) : 0;   // +1 = self loop
    int xval = v;
    #pragma unroll
    for (int o = 1; o < 32; o <<= 1) {
        int y = __shfl_up_sync(~0u, xval, o);
        if (lane >= o) xval += y;
    }
    if (lane == 31) wsum[wid] = xval;
    __syncthreads();
    if (wid == 0) {
        int w = wsum[lane];
        #pragma unroll
        for (int o = 1; o < 32; o <<= 1) {
            int y = __shfl_up_sync(~0u, w, o);
            if (lane >= o) w += y;
        }
        wsum[lane] = w;
    }
    __syncthreads();
    int incl = xval + (wid ? wsum[wid - 1] : 0);
    if (i < NN) g_rowptr[i] = incl - v;       // local exclusive
    if (t == 1023) g_bsum[blockIdx.x] = incl;
}
__global__ void k_scan2(int nb) {
    __shared__ int s[128];
    int t = threadIdx.x;
    int v = (t < nb) ? g_bsum[t] : 0;
    s[t] = v;
    __syncthreads();
    #pragma unroll
    for (int off = 1; off < 128; off <<= 1) {
        int y = (t >= off) ? s[t - off] : 0;
        __syncthreads();
        s[t] += y;
        __syncthreads();
    }
    if (t < nb) g_boff[t] = s[t] - v;   // exclusive
}
__global__ void k_scan3(int Etot) {
    int i = blockIdx.x * blockDim.x + threadIdx.x;
    if (i < NN) g_rowptr[i] += g_boff[i >> 10];
    if (i == 0) g_rowptr[NN] = Etot;
}
__global__ void k_scatter(const int* __restrict__ ei, int E) {
    int i = blockIdx.x * blockDim.x + threadIdx.x;
    if (i >= E + NN) return;
    int s, p;
    if (i < E) {
        s = ei[i];
        int d = ei[E + i];
        if (d < 0 || d >= NN) return;
        p = g_rowptr[d] + g_epos[i];
    } else {
        int v = i - E;
        s = v;
        p = g_rowptr[v] + g_deg[v];     // self loop occupies last slot
    }
    if (p >= 0 && p < ET_MAX) g_esrc[p] = s;
}

// ------ layer-1 aggregation + fused layer-2 projection (warp per dst) -------
// 4 edges per iteration: lane = e*8+f (e = edge slot, f = feature octet).
__global__ void k_agg1(const float* __restrict__ b1, const float* __restrict__ W2,
                       const float* __restrict__ a2s, const float* __restrict__ a2d) {
    int v    = (blockIdx.x * blockDim.x + threadIdx.x) >> 5;
    int lane = threadIdx.x & 31;
    if (v >= NN) return;
    int beg = g_rowptr[v], end = g_rowptr[v + 1];
    float dv = g_d1[v];
    const int e = lane >> 3, f = lane & 7;

    float den = 0.f;
    float acc[8] = {};
    for (int base = beg; base < end; base += 32) {
        int cnt = min(32, end - base);
        int u = 0; float ew = 0.f;
        if (lane < cnt) {
            u = g_esrc[base + lane];
            float t = g_s1[u] + dv;
            t = t > 0.f ? t : 0.2f * t;
            ew = __expf(t);
        }
        // denominator: each lane holds one edge's weight (0 if invalid)
        float dsum = ew;
        #pragma unroll
        for (int o = 16; o; o >>= 1) dsum += __shfl_xor_sync(~0u, dsum, o);
        den += dsum;

        int steps = (cnt + 3) >> 2;
        for (int j = 0; j < steps; j++) {
            int idx = 4 * j + e;                       // 0..31 always valid shfl src
            int   uu = __shfl_sync(~0u, u,  idx);
            float wt = __shfl_sync(~0u, ew, idx);      // 0 for tail edges
            float4 hv = g_h1f[uu * 8 + f];             // 8 fp16 features, 16B aligned
            float2 f0 = __half22float2(*(__half2*)&hv.x);
            float2 f1 = __half22float2(*(__half2*)&hv.y);
            float2 f2 = __half22float2(*(__half2*)&hv.z);
            float2 f3 = __half22float2(*(__half2*)&hv.w);
            acc[0] += wt * f0.x; acc[1] += wt * f0.y;
            acc[2] += wt * f1.x; acc[3] += wt * f1.y;
            acc[4] += wt * f2.x; acc[5] += wt * f2.y;
            acc[6] += wt * f3.x; acc[7] += wt * f3.y;
        }
    }
    // combine the 4 edge-slot partial sums (lanes f, f+8, f+16, f+24)
    #pragma unroll
    for (int i = 0; i < 8; i++) {
        acc[i] += __shfl_xor_sync(~0u, acc[i], 8);
        acc[i] += __shfl_xor_sync(~0u, acc[i], 16);
    }
    float inv = 1.f / den;
    float4 bA = *(const float4*)&b1[f * 8];
    float4 bB = *(const float4*)&b1[f * 8 + 4];
    float hr[8];
    hr[0] = fmaxf(acc[0] * inv + bA.x, 0.f);
    hr[1] = fmaxf(acc[1] * inv + bA.y, 0.f);
    hr[2] = fmaxf(acc[2] * inv + bA.z, 0.f);
    hr[3] = fmaxf(acc[3] * inv + bA.w, 0.f);
    hr[4] = fmaxf(acc[4] * inv + bB.x, 0.f);
    hr[5] = fmaxf(acc[5] * inv + bB.y, 0.f);
    hr[6] = fmaxf(acc[6] * inv + bB.z, 0.f);
    hr[7] = fmaxf(acc[7] * inv + bB.w, 0.f);

    // fused layer-2 projection: partial over this lane's 8 features
    float c0 = 0.f, c1 = 0.f;
    #pragma unroll
    for (int i = 0; i < 8; i++) {
        float2 w = *(const float2*)&W2[(f * 8 + i) * 2];
        c0 += hr[i] * w.x;
        c1 += hr[i] * w.y;
    }
    #pragma unroll
    for (int o = 1; o < 8; o <<= 1) {
        c0 += __shfl_xor_sync(~0u, c0, o);
        c1 += __shfl_xor_sync(~0u, c1, o);
    }
    if (!lane) {
        float s2v = c0 * a2s[0] + c1 * a2s[1];
        float d2v = c0 * a2d[0] + c1 * a2d[1];
        g_p2[v] = make_float4(c0, c1, s2v, d2v);
    }
}

// ---------------- layer-2 aggregation (warp per dst node) -------------------
__global__ void k_agg2(float* __restrict__ out, const float* __restrict__ b2) {
    int v    = (blockIdx.x * blockDim.x + threadIdx.x) >> 5;
    int lane = threadIdx.x & 31;
    if (v >= NN) return;
    int beg = g_rowptr[v], end = g_rowptr[v + 1];
    float dv = g_p2[v].w;

    float den = 0.f, ax = 0.f, ay = 0.f;
    for (int j = beg + lane; j < end; j += 32) {
        int u = g_esrc[j];
        float4 p = g_p2[u];                 // (h2.x, h2.y, s2, d2) one sector
        float t = p.z + dv;
        t = t > 0.f ? t : 0.2f * t;
        float wt = __expf(t);
        den += wt;
        ax  += wt * p.x;
        ay  += wt * p.y;
    }
    #pragma unroll
    for (int o = 16; o; o >>= 1) {
        den += __shfl_xor_sync(~0u, den, o);
        ax  += __shfl_xor_sync(~0u, ax, o);
        ay  += __shfl_xor_sync(~0u, ay, o);
    }
    if (!lane) {
        float inv = 1.f / den;
        out[v * 2 + 0] = ax * inv + b2[0];
        out[v * 2 + 1] = ay * inv + b2[1];
    }
}

// ---------------- second output: edge_index passthrough as float ------------
__global__ void k_ecpy4(const int* __restrict__ ei, float* __restrict__ out, int n4) {
    int i = blockIdx.x * blockDim.x + threadIdx.x;
    if (i < n4) {
        int4 v = ((const int4*)ei)[i];
        float4 f = make_float4((float)v.x, (float)v.y, (float)v.z, (float)v.w);
        ((float4*)out)[i] = f;
    }
}
__global__ void k_ecpy_tail(const int* __restrict__ ei, float* __restrict__ out,
                            int start, int n) {
    int i = start + blockIdx.x * blockDim.x + threadIdx.x;
    if (i < n) out[i] = (float)ei[i];
}

// ---------------- launch -----------------------------------------------------
extern "C" void kernel_launch(void* const* d_in, const int* in_sizes, int n_in,
                              void* d_out, int out_size) {
    const float* x   = (const float*)d_in[0];
    const int*   ei  = (const int*)  d_in[1];
    const float* W1  = (const float*)d_in[2];
    const float* a1s = (const float*)d_in[3];
    const float* a1d = (const float*)d_in[4];
    const float* b1  = (const float*)d_in[5];
    const float* W2  = (const float*)d_in[6];
    const float* a2s = (const float*)d_in[7];
    const float* a2d = (const float*)d_in[8];
    const float* b2  = (const float*)d_in[9];
    float* out = (float*)d_out;

    int E = in_sizes[1] / 2;       // 1,600,000
    int Etot = E + NN;
    int nb = (NN + 1023) / 1024;   // 98 scan blocks

    cudaStream_t s2 = g_hx.s2;

    // fork: side stream joins capture via event on the main (default) stream
    cudaEventRecord(g_hx.evA, 0);
    cudaStreamWaitEvent(s2, g_hx.evA, 0);

    // main stream: GEMM (with fused s1/d1)
    k_gemm1<<<(NN + 63) / 64, 256>>>(x, W1, a1s, a1d);

    // side stream: CSR build (independent of GEMM)
    k_zero_deg<<<(NN + 255) / 256, 256, 0, s2>>>();
    k_deg<<<(E + 255) / 256, 256, 0, s2>>>(ei, E);
    k_scan1<<<nb, 1024, 0, s2>>>();
    k_scan2<<<1, 128, 0, s2>>>(nb);
    k_scan3<<<(NN + 255) / 256, 256, 0, s2>>>(Etot);
    k_scatter<<<(Etot + 255) / 256, 256, 0, s2>>>(ei, E);
    cudaEventRecord(g_hx.evB, s2);

    // side stream: independent edge_index copy (overlaps with agg1/agg2)
    int extra = out_size - NN * 2;
    if (extra > 0) {
        int n = extra < 2 * E ? extra : 2 * E;
        int n4 = n / 4;
        if (n4 > 0)
            k_ecpy4<<<(n4 + 255) / 256, 256, 0, s2>>>(ei, out + NN * 2, n4);
        if (n - n4 * 4 > 0)
            k_ecpy_tail<<<1, 256, 0, s2>>>(ei, out + NN * 2, n4 * 4, n);
    }
    cudaEventRecord(g_hx.evC, s2);

    // main stream waits for CSR, then aggregates
    cudaStreamWaitEvent(0, g_hx.evB, 0);
    k_agg1<<<(NN * 32 + 255) / 256, 256>>>(b1, W2, a2s, a2d);
    k_agg2<<<(NN * 32 + 255) / 256, 256>>>(out, b2);

    // join: main stream waits for side-stream tail (required for capture)
    cudaStreamWaitEvent(0, g_hx.evC, 0);
}

// round 14
// speedup vs baseline: 1.1248x; 1.1248x over previous
#include <cuda_runtime.h>
#include <cuda_fp16.h>

#define NN   100000
#define EE_MAX 1600000
#define ET_MAX (NN + EE_MAX)
#define FIN  165
#define HID  64

// ---------------- scratch (device globals; no allocation allowed) ------------
__device__ float4 g_h1f[NN * 8];        // layer-1 features fp16: 8 float4 = 32 half2 per row
__device__ float  g_s1[NN], g_d1[NN];
__device__ float4 g_p2[NN];             // packed (h2.x, h2.y, s2, d2)
__device__ int    g_deg[NN];
__device__ int    g_epos[EE_MAX];       // within-row position of each edge
__device__ int    g_rowptr[NN + 1];
__device__ int    g_esrc[ET_MAX];
__device__ int    g_bsum[128], g_boff[128];

// side stream + events for capture fork/join (host-side resources, module load)
struct HxStreams {
    cudaStream_t s2;
    cudaEvent_t evA, evB, evC;
    HxStreams() {
        cudaStreamCreateWithFlags(&s2, cudaStreamNonBlocking);
        cudaEventCreateWithFlags(&evA, cudaEventDisableTiming);
        cudaEventCreateWithFlags(&evB, cudaEventDisableTiming);
        cudaEventCreateWithFlags(&evC, cudaEventDisableTiming);
    }
};
static HxStreams g_hx;

// ------- GEMM1: h1 = x @ W1 (100000x165 @ 165x64), fused s1/d1 epilogue -----
__global__ void k_gemm1(const float* __restrict__ x, const float* __restrict__ W1,
                        const float* __restrict__ a1s, const float* __restrict__ a1d) {
    __shared__ float As[16][64];   // As[kk][row]
    __shared__ float Bs[16][64];   // Bs[kk][col]
    const int row0 = blockIdx.x * 64;
    const int tid  = threadIdx.x;        // 0..255
    const int tx   = tid & 15;           // col group (4 cols each)
    const int ty   = tid >> 4;           // row group (4 rows each)
    float acc[4][4] = {};

    for (int k0 = 0; k0 < FIN; k0 += 16) {
        #pragma unroll
        for (int i = 0; i < 4; i++) {
            int idx = tid * 4 + i;          // 0..1023
            int r  = idx >> 4;              // 0..63
            int kk = idx & 15;
            int gr = row0 + r, gk = k0 + kk;
            As[kk][r] = (gr < NN && gk < FIN) ? x[gr * FIN + gk] : 0.f;
        }
        #pragma unroll
        for (int i = 0; i < 4; i++) {
            int idx = tid * 4 + i;
            int kk = idx >> 6;              // 0..15
            int c  = idx & 63;
            int gk = k0 + kk;
            Bs[kk][c] = (gk < FIN) ? W1[gk * HID + c] : 0.f;
        }
        __syncthreads();
        #pragma unroll
        for (int kk = 0; kk < 16; kk++) {
            float a[4], b[4];
            #pragma unroll
            for (int i = 0; i < 4; i++) a[i] = As[kk][ty * 4 + i];
            #pragma unroll
            for (int i = 0; i < 4; i++) b[i] = Bs[kk][tx * 4 + i];
            #pragma unroll
            for (int i = 0; i < 4; i++)
                #pragma unroll
                for (int j = 0; j < 4; j++)
                    acc[i][j] += a[i] * b[j];
        }
        __syncthreads();
    }

    // store h1 as fp16 (cols tx*4 .. tx*4+3 -> half2 slots tx*2, tx*2+1 of the row)
    __half2* h1h = (__half2*)g_h1f;
    #pragma unroll
    for (int i = 0; i < 4; i++) {
        int gr = row0 + ty * 4 + i;
        if (gr < NN) {
            h1h[gr * 32 + tx * 2 + 0] = __floats2half2_rn(acc[i][0], acc[i][1]);
            h1h[gr * 32 + tx * 2 + 1] = __floats2half2_rn(acc[i][2], acc[i][3]);
        }
    }

    // fused epilogue: s1[r] = h[r]·a1s, d1[r] = h[r]·a1d (fp32, reduce 16 tx lanes)
    float4 as4 = *(const float4*)&a1s[tx * 4];
    float4 ad4 = *(const float4*)&a1d[tx * 4];
    #pragma unroll
    for (int i = 0; i < 4; i++) {
        float ps = acc[i][0] * as4.x + acc[i][1] * as4.y + acc[i][2] * as4.z + acc[i][3] * as4.w;
        float pd = acc[i][0] * ad4.x + acc[i][1] * ad4.y + acc[i][2] * ad4.z + acc[i][3] * ad4.w;
        #pragma unroll
        for (int o = 1; o < 16; o <<= 1) {
            ps += __shfl_xor_sync(~0u, ps, o);
            pd += __shfl_xor_sync(~0u, pd, o);
        }
        int gr = row0 + ty * 4 + i;
        if (tx == 0 && gr < NN) { g_s1[gr] = ps; g_d1[gr] = pd; }
    }
}

// ---------------- CSR construction ------------------------------------------
__global__ void k_zero_deg() {
    int i = blockIdx.x * blockDim.x + threadIdx.x;
    if (i < NN) g_deg[i] = 0;
}
__global__ void k_deg(const int* __restrict__ ei, int E) {
    int i = blockIdx.x * blockDim.x + threadIdx.x;
    if (i < E) {
        int d = ei[E + i];
        int p = 0;
        if (d >= 0 && d < NN) p = atomicAdd(&g_deg[d], 1);
        g_epos[i] = p;
    }
}
__global__ void k_scan1() {
    __shared__ int wsum[32];
    int i = blockIdx.x * 1024 + threadIdx.x;
    int t = threadIdx.x;
    int lane = t & 31, wid = t >> 5;
    int v = (i < NN) ? (g_deg[i] + 1) : 0;   // +1 = self loop
    int xval = v;
    #pragma unroll
    for (int o = 1; o < 32; o <<= 1) {
        int y = __shfl_up_sync(~0u, xval, o);
        if (lane >= o) xval += y;
    }
    if (lane == 31) wsum[wid] = xval;
    __syncthreads();
    if (wid == 0) {
        int w = wsum[lane];
        #pragma unroll
        for (int o = 1; o < 32; o <<= 1) {
            int y = __shfl_up_sync(~0u, w, o);
            if (lane >= o) w += y;
        }
        wsum[lane] = w;
    }
    __syncthreads();
    int incl = xval + (wid ? wsum[wid - 1] : 0);
    if (i < NN) g_rowptr[i] = incl - v;       // local exclusive
    if (t == 1023) g_bsum[blockIdx.x] = incl;
}
__global__ void k_scan2(int nb) {
    __shared__ int s[128];
    int t = threadIdx.x;
    int v = (t < nb) ? g_bsum[t] : 0;
    s[t] = v;
    __syncthreads();
    #pragma unroll
    for (int off = 1; off < 128; off <<= 1) {
        int y = (t >= off) ? s[t - off] : 0;
        __syncthreads();
        s[t] += y;
        __syncthreads();
    }
    if (t < nb) g_boff[t] = s[t] - v;   // exclusive
}
__global__ void k_scan3(int Etot) {
    int i = blockIdx.x * blockDim.x + threadIdx.x;
    if (i < NN) g_rowptr[i] += g_boff[i >> 10];
    if (i == 0) g_rowptr[NN] = Etot;
}
__global__ void k_scatter(const int* __restrict__ ei, int E) {
    int i = blockIdx.x * blockDim.x + threadIdx.x;
    if (i >= E + NN) return;
    int s, p;
    if (i < E) {
        s = ei[i];
        int d = ei[E + i];
        if (d < 0 || d >= NN) return;
        p = g_rowptr[d] + g_epos[i];
    } else {
        int v = i - E;
        s = v;
        p = g_rowptr[v] + g_deg[v];     // self loop occupies last slot
    }
    if (p >= 0 && p < ET_MAX) g_esrc[p] = s;
}

// ------ layer-1 aggregation + fused layer-2 projection (warp per dst) -------
// R8-proven shape: one edge per inner iteration, all 32 lanes gather one
// 128B row coalesced. unroll 4 -> 4 gathers in flight (MLP).
__global__ void k_agg1(const float* __restrict__ b1, const float* __restrict__ W2,
                       const float* __restrict__ a2s, const float* __restrict__ a2d) {
    int v    = (blockIdx.x * blockDim.x + threadIdx.x) >> 5;
    int lane = threadIdx.x & 31;
    if (v >= NN) return;
    int beg = g_rowptr[v], end = g_rowptr[v + 1];
    float dv = g_d1[v];
    const __half2* h1h = (const __half2*)g_h1f;

    float den = 0.f;
    float2 acc = make_float2(0.f, 0.f);
    for (int base = beg; base < end; base += 32) {
        int cnt = min(32, end - base);
        int u = 0; float ew = 0.f;
        if (base + lane < end) {
            u = g_esrc[base + lane];
            float t = g_s1[u] + dv;
            t = t > 0.f ? t : 0.2f * t;
            ew = __expf(t);
        }
        #pragma unroll 4
        for (int t = 0; t < cnt; t++) {
            int   uu = __shfl_sync(~0u, u, t);
            float wt = __shfl_sync(~0u, ew, t);
            den += wt;
            float2 f = __half22float2(h1h[uu * 32 + lane]);
            acc.x += wt * f.x;
            acc.y += wt * f.y;
        }
    }
    float inv = 1.f / den;
    float2 bb = *(const float2*)&b1[lane * 2];
    float rx = fmaxf(acc.x * inv + bb.x, 0.f);   // relu'd hr row, comps 2*lane, 2*lane+1
    float ry = fmaxf(acc.y * inv + bb.y, 0.f);

    // fused layer-2 projection: h2 = hr @ W2  (W2 is [64][2] row-major)
    float4 w4 = *(const float4*)&W2[lane * 4];
    float c0 = rx * w4.x + ry * w4.z;
    float c1 = rx * w4.y + ry * w4.w;
    #pragma unroll
    for (int o = 16; o; o >>= 1) {
        c0 += __shfl_xor_sync(~0u, c0, o);
        c1 += __shfl_xor_sync(~0u, c1, o);
    }
    if (!lane) {
        float s2v = c0 * a2s[0] + c1 * a2s[1];
        float d2v = c0 * a2d[0] + c1 * a2d[1];
        g_p2[v] = make_float4(c0, c1, s2v, d2v);
    }
}

// ---------------- layer-2 aggregation (warp per dst node) -------------------
__global__ void k_agg2(float* __restrict__ out, const float* __restrict__ b2) {
    int v    = (blockIdx.x * blockDim.x + threadIdx.x) >> 5;
    int lane = threadIdx.x & 31;
    if (v >= NN) return;
    int beg = g_rowptr[v], end = g_rowptr[v + 1];
    float dv = g_p2[v].w;

    float den = 0.f, ax = 0.f, ay = 0.f;
    #pragma unroll 4
    for (int j = beg + lane; j < end; j += 32) {
        int u = g_esrc[j];
        float4 p = g_p2[u];                 // (h2.x, h2.y, s2, d2) one sector
        float t = p.z + dv;
        t = t > 0.f ? t : 0.2f * t;
        float wt = __expf(t);
        den += wt;
        ax  += wt * p.x;
        ay  += wt * p.y;
    }
    #pragma unroll
    for (int o = 16; o; o >>= 1) {
        den += __shfl_xor_sync(~0u, den, o);
        ax  += __shfl_xor_sync(~0u, ax, o);
        ay  += __shfl_xor_sync(~0u, ay, o);
    }
    if (!lane) {
        float inv = 1.f / den;
        out[v * 2 + 0] = ax * inv + b2[0];
        out[v * 2 + 1] = ay * inv + b2[1];
    }
}

// ---------------- second output: edge_index passthrough as float ------------
__global__ void k_ecpy4(const int* __restrict__ ei, float* __restrict__ out, int n4) {
    int i = blockIdx.x * blockDim.x + threadIdx.x;
    if (i < n4) {
        int4 v = ((const int4*)ei)[i];
        float4 f = make_float4((float)v.x, (float)v.y, (float)v.z, (float)v.w);
        ((float4*)out)[i] = f;
    }
}
__global__ void k_ecpy_tail(const int* __restrict__ ei, float* __restrict__ out,
                            int start, int n) {
    int i = start + blockIdx.x * blockDim.x + threadIdx.x;
    if (i < n) out[i] = (float)ei[i];
}

// ---------------- launch -----------------------------------------------------
extern "C" void kernel_launch(void* const* d_in, const int* in_sizes, int n_in,
                              void* d_out, int out_size) {
    const float* x   = (const float*)d_in[0];
    const int*   ei  = (const int*)  d_in[1];
    const float* W1  = (const float*)d_in[2];
    const float* a1s = (const float*)d_in[3];
    const float* a1d = (const float*)d_in[4];
    const float* b1  = (const float*)d_in[5];
    const float* W2  = (const float*)d_in[6];
    const float* a2s = (const float*)d_in[7];
    const float* a2d = (const float*)d_in[8];
    const float* b2  = (const float*)d_in[9];
    float* out = (float*)d_out;

    int E = in_sizes[1] / 2;       // 1,600,000
    int Etot = E + NN;
    int nb = (NN + 1023) / 1024;   // 98 scan blocks

    cudaStream_t s2 = g_hx.s2;

    // fork: side stream joins capture via event on the main (default) stream
    cudaEventRecord(g_hx.evA, 0);
    cudaStreamWaitEvent(s2, g_hx.evA, 0);

    // main stream: GEMM (with fused s1/d1)
    k_gemm1<<<(NN + 63) / 64, 256>>>(x, W1, a1s, a1d);

    // side stream: CSR build (independent of GEMM)
    k_zero_deg<<<(NN + 255) / 256, 256, 0, s2>>>();
    k_deg<<<(E + 255) / 256, 256, 0, s2>>>(ei, E);
    k_scan1<<<nb, 1024, 0, s2>>>();
    k_scan2<<<1, 128, 0, s2>>>(nb);
    k_scan3<<<(NN + 255) / 256, 256, 0, s2>>>(Etot);
    k_scatter<<<(Etot + 255) / 256, 256, 0, s2>>>(ei, E);
    cudaEventRecord(g_hx.evB, s2);

    // side stream: independent edge_index copy (overlaps with agg1/agg2)
    int extra = out_size - NN * 2;
    if (extra > 0) {
        int n = extra < 2 * E ? extra : 2 * E;
        int n4 = n / 4;
        if (n4 > 0)
            k_ecpy4<<<(n4 + 255) / 256, 256, 0, s2>>>(ei, out + NN * 2, n4);
        if (n - n4 * 4 > 0)
            k_ecpy_tail<<<1, 256, 0, s2>>>(ei, out + NN * 2, n4 * 4, n);
    }
    cudaEventRecord(g_hx.evC, s2);

    // main stream waits for CSR, then aggregates
    cudaStreamWaitEvent(0, g_hx.evB, 0);
    k_agg1<<<(NN * 32 + 255) / 256, 256>>>(b1, W2, a2s, a2d);
    k_agg2<<<(NN * 32 + 255) / 256, 256>>>(out, b2);

    // join: main stream waits for side-stream tail (required for capture)
    cudaStreamWaitEvent(0, g_hx.evC, 0);
}